// round 13
// baseline (speedup 1.0000x reference)
#include <cuda_runtime.h>
#include <cuda_bf16.h>
#include <stdint.h>

// ---------------------------------------------------------------------------
// LennardJones, single persistent kernel (1 graph node).
// Outputs (flattened, concatenated):
//   d_out[0]              = potential_energy = 0.5 * (sum_n acc.w - E*e0)
//   d_out[1 .. 1+3N)      = forces          = -0.5 * analytic   (exact identity)
//   d_out[1+3N .. 1+6N)   = analytic_force  = segsum(f_scalar * bv)
//
// Phases (all inside one launch, separated by monotonic spin barriers):
//   0: zero g_acc (grid-stride)
//   1: per-edge RED.v4 {fs*x,fs*y,fs*z,pe} into g_acc  (op-count floor)
//   2: finalize: write force arrays, reduce .w; last-arriving CTA writes PE
// Cross-replay: g_bar is a monotonic arrival counter; g_gen holds the epoch
// base updated by the last CTA each call -> identical work every replay.
// Grid = 148*4 CTAs @ __launch_bounds__(256,4) -> all co-resident (no deadlock).
// ---------------------------------------------------------------------------

#define SCRATCH_CAP 131072   // >= n_nodes (100000)
#define NUM_CTAS    592      // 148 SMs * 4 CTAs/SM (co-residency guaranteed)

__device__ float4 g_acc[SCRATCH_CAP];        // per-node {fx,fy,fz,pe_raw}
__device__ double g_pe;                       // PE scratch (reset by last CTA)
__device__ unsigned long long g_bar;          // monotonic barrier arrivals
__device__ unsigned long long g_gen;          // epoch base (completed arrivals)

// e0 = 4*((1/3)^12 - (1/3)^6) in double
#define E0_D (-5.479441744238777e-03)

// ---------------------------------------------------------------------------

__device__ __forceinline__ unsigned long long ld_bar() {
    unsigned long long v;
    asm volatile("ld.global.cg.u64 %0, [%1];" : "=l"(v) : "l"(&g_bar));
    return v;
}

// CTA-wide barrier arrive+spin: tid 0 arrives and spins, then block syncs.
__device__ __forceinline__ void grid_barrier(unsigned long long target) {
    __syncthreads();
    if (threadIdx.x == 0) {
        atomicAdd(&g_bar, 1ULL);
        while (ld_bar() < target) __nanosleep(128);
    }
    __syncthreads();
}

__device__ __forceinline__ void edge_op(float x, float y, float z, int n) {
    float r2  = fmaf(x, x, fmaf(y, y, z * z));
    float inv = __fdividef(1.0f, r2);
    float c6  = inv * inv * inv;
    float c12 = c6 * c6;
    float fs  = -24.0f * (2.0f * c12 - c6) * inv;
    float pe  = 4.0f * (c12 - c6);
    float4* p = &g_acc[n];
    asm volatile("red.global.add.v4.f32 [%0], {%1,%2,%3,%4};"
                 :: "l"(p), "f"(fs * x), "f"(fs * y), "f"(fs * z), "f"(pe)
                 : "memory");
}

__global__ void __launch_bounds__(256, 4)
lj_fused(const float* __restrict__ bv, const int* __restrict__ dst,
         float* __restrict__ out, int E, int N, double pe_const) {
    const int t      = blockIdx.x * blockDim.x + threadIdx.x;
    const int stride = gridDim.x * blockDim.x;
    const unsigned long long C    = gridDim.x;
    const unsigned long long base = g_gen;  // stable: written before this launch

    // ---- phase 0: zero accumulators ----
    for (int n = t; n < N; n += stride)
        g_acc[n] = make_float4(0.f, 0.f, 0.f, 0.f);
    __threadfence();
    grid_barrier(base + C);

    // ---- phase 1: per-edge scatter ----
    const int T = (E + 3) >> 2;  // 4-edge tiles
    const float4* bv4  = reinterpret_cast<const float4*>(bv);
    const int4*   dst4 = reinterpret_cast<const int4*>(dst);
    for (int tt = t; tt < T; tt += stride) {
        int e0 = tt * 4;
        if (e0 + 3 < E) {
            float4 a = bv4[3 * tt + 0];
            float4 b = bv4[3 * tt + 1];
            float4 c = bv4[3 * tt + 2];
            int4   d = dst4[tt];
            edge_op(a.x, a.y, a.z, d.x);
            edge_op(a.w, b.x, b.y, d.y);
            edge_op(b.z, b.w, c.x, d.z);
            edge_op(c.y, c.z, c.w, d.w);
        } else {
            for (int e = e0; e < E; e++)
                edge_op(bv[3 * e], bv[3 * e + 1], bv[3 * e + 2], dst[e]);
        }
    }
    __threadfence();
    grid_barrier(base + 2 * C);

    // ---- phase 2: finalize ----
    float w = 0.0f;
    for (int n = t; n < N; n += stride) {
        float4 a;
        asm volatile("ld.global.cg.v4.f32 {%0,%1,%2,%3}, [%4];"
                     : "=f"(a.x), "=f"(a.y), "=f"(a.z), "=f"(a.w)
                     : "l"(&g_acc[n]));
        w += a.w;
        float* f  = out + 1 + 3 * n;
        float* af = out + 1 + 3 * N + 3 * n;
        f[0]  = -0.5f * a.x;  f[1]  = -0.5f * a.y;  f[2]  = -0.5f * a.z;
        af[0] = a.x;          af[1] = a.y;          af[2] = a.z;
    }

    // CTA reduction of w
    __shared__ float sred[8];
    unsigned lane = threadIdx.x & 31u;
    unsigned warp = threadIdx.x >> 5;
    #pragma unroll
    for (int off = 16; off > 0; off >>= 1)
        w += __shfl_down_sync(0xFFFFFFFFu, w, off);
    if (lane == 0) sred[warp] = w;
    __syncthreads();

    if (threadIdx.x == 0) {
        float v = 0.0f;
        #pragma unroll
        for (int j = 0; j < 8; j++) v += sred[j];
        atomicAdd(&g_pe, (double)v);
        __threadfence();
        unsigned long long old = atomicAdd(&g_bar, 1ULL);
        if (old == base + 3 * C - 1) {
            // last CTA: all PE contributions are fenced-in
            double total = atomicAdd(&g_pe, 0.0);
            out[0] = (float)(0.5 * (total - pe_const));
            g_pe  = 0.0;            // reset for next replay
            g_gen = base + 3 * C;   // advance epoch
        }
    }
}

// ---------------------------------------------------------------------------
// Fallback path for N > SCRATCH_CAP (not expected at N=100000).

__global__ void lj_main_direct(const float* __restrict__ bv,
                               const int* __restrict__ dst,
                               float* __restrict__ acc, int E) {
    int e = blockIdx.x * blockDim.x + threadIdx.x;
    float pe = 0.0f;
    if (e < E) {
        float x = bv[3 * e], y = bv[3 * e + 1], z = bv[3 * e + 2];
        int n = dst[e];
        float r2  = fmaf(x, x, fmaf(y, y, z * z));
        float inv = __fdividef(1.0f, r2);
        float c6  = inv * inv * inv;
        float c12 = c6 * c6;
        float fs  = -24.0f * (2.0f * c12 - c6) * inv;
        atomicAdd(acc + 3 * n + 0, fs * x);
        atomicAdd(acc + 3 * n + 1, fs * y);
        atomicAdd(acc + 3 * n + 2, fs * z);
        pe = 4.0f * (c12 - c6);
    }
    #pragma unroll
    for (int off = 16; off > 0; off >>= 1)
        pe += __shfl_down_sync(0xFFFFFFFFu, pe, off);
    if ((threadIdx.x & 31u) == 0) atomicAdd(&g_pe, (double)pe);
}

__global__ void finalize_direct(float* __restrict__ out, int N, double pe_const) {
    int i = blockIdx.x * blockDim.x + threadIdx.x;
    int total = 3 * N;
    if (i < total) out[1 + i] = -0.5f * out[1 + total + i];
    if (i == 0) {
        out[0] = (float)(0.5 * (g_pe - pe_const));
        g_pe = 0.0;
    }
}

// ---------------------------------------------------------------------------

extern "C" void kernel_launch(void* const* d_in, const int* in_sizes, int n_in,
                              void* d_out, int out_size) {
    const float* bv  = (const float*)d_in[0];
    const int*   dst = (const int*)d_in[1];
    float* out = (float*)d_out;

    int E = in_sizes[1];
    int N = (out_size - 1) / 6;
    double pe_const = (double)E * E0_D;

    if (N <= SCRATCH_CAP) {
        lj_fused<<<NUM_CTAS, 256>>>(bv, dst, out, E, N, pe_const);
    } else {
        float* acc = out + 1 + 3 * N;
        cudaMemsetAsync(acc, 0, (size_t)(3 * N) * sizeof(float), 0);
        int threads = 256;
        int blocks = (E + threads - 1) / threads;
        lj_main_direct<<<blocks, threads>>>(bv, dst, acc, E);
        int b2 = (3 * N + threads - 1) / threads;
        finalize_direct<<<b2, threads>>>(out, N, pe_const);
    }
}

// round 14
// speedup vs baseline: 1.1352x; 1.1352x over previous
#include <cuda_runtime.h>
#include <cuda_bf16.h>
#include <stdint.h>

// ---------------------------------------------------------------------------
// LennardJones: 2 memset nodes + 1 fused persistent kernel.
// Outputs (flattened, concatenated):
//   d_out[0]              = potential_energy = 0.5 * (sum_n acc.w - E*e0)
//   d_out[1 .. 1+3N)      = forces          = -0.5 * analytic   (exact identity)
//   d_out[1+3N .. 1+6N)   = analytic_force  = segsum(f_scalar * bv)
//
// Graph: memset(g_acc)=~free, memset(g_misc)=~free, lj_fused.
// Fused kernel: phase 1 (per-edge RED.v4 scatter, PE in free .w lane) ->
// grid barrier -> phase 2 (finalize + PE reduction; last CTA writes out[0]).
// R13 profile: L2=56.7%, occ=48.5% (reg-limited at 56) -> this round raises
// occupancy to 75% (512thr x 3 CTA/SM, <=42 regs) to push the L2 atomic
// pipe toward saturation.
// ---------------------------------------------------------------------------

#define SCRATCH_CAP 131072   // >= n_nodes (100000)
#define FUSED_CTAS  444      // 148 SMs * 3 CTAs/SM, all co-resident
#define FUSED_THR   512

__device__ float4 g_acc[SCRATCH_CAP];   // per-node {fx,fy,fz,pe_raw}
struct Misc { double pe; unsigned long long bar; };
__device__ Misc g_misc;                 // zeroed by memset each call

// e0 = 4*((1/3)^12 - (1/3)^6) in double
#define E0_D (-5.479441744238777e-03)

// ---------------------------------------------------------------------------

__device__ __forceinline__ unsigned long long ld_bar() {
    unsigned long long v;
    asm volatile("ld.global.cg.u64 %0, [%1];" : "=l"(v) : "l"(&g_misc.bar));
    return v;
}

__device__ __forceinline__ void edge_op(float x, float y, float z, int n) {
    float r2  = fmaf(x, x, fmaf(y, y, z * z));
    float inv = __fdividef(1.0f, r2);
    float c6  = inv * inv * inv;
    float c12 = c6 * c6;
    float fs  = -24.0f * (2.0f * c12 - c6) * inv;
    float pe  = 4.0f * (c12 - c6);
    float4* p = &g_acc[n];
    asm volatile("red.global.add.v4.f32 [%0], {%1,%2,%3,%4};"
                 :: "l"(p), "f"(fs * x), "f"(fs * y), "f"(fs * z), "f"(pe)
                 : "memory");
}

__global__ void __launch_bounds__(FUSED_THR, 3)
lj_fused(const float* __restrict__ bv, const int* __restrict__ dst,
         float* __restrict__ out, int E, int N, double pe_const) {
    const int t      = blockIdx.x * blockDim.x + threadIdx.x;
    const int stride = gridDim.x * blockDim.x;
    const unsigned long long C = gridDim.x;

    // ---- phase 1: per-edge scatter (g_acc pre-zeroed by memset node) ----
    const int T = (E + 3) >> 2;  // 4-edge tiles
    const float4* bv4  = reinterpret_cast<const float4*>(bv);
    const int4*   dst4 = reinterpret_cast<const int4*>(dst);
    for (int tt = t; tt < T; tt += stride) {
        int e0 = tt * 4;
        if (e0 + 3 < E) {
            float4 a = bv4[3 * tt + 0];
            float4 b = bv4[3 * tt + 1];
            float4 c = bv4[3 * tt + 2];
            int4   d = dst4[tt];
            edge_op(a.x, a.y, a.z, d.x);
            edge_op(a.w, b.x, b.y, d.y);
            edge_op(b.z, b.w, c.x, d.z);
            edge_op(c.y, c.z, c.w, d.w);
        } else {
            for (int e = e0; e < E; e++)
                edge_op(bv[3 * e], bv[3 * e + 1], bv[3 * e + 2], dst[e]);
        }
    }
    __threadfence();

    // ---- grid barrier (all CTAs co-resident by launch_bounds) ----
    __syncthreads();
    if (threadIdx.x == 0) {
        atomicAdd(&g_misc.bar, 1ULL);
        while (ld_bar() < C) __nanosleep(128);
    }
    __syncthreads();

    // ---- phase 2: finalize ----
    float w = 0.0f;
    for (int n = t; n < N; n += stride) {
        float4 a;
        asm volatile("ld.global.cg.v4.f32 {%0,%1,%2,%3}, [%4];"
                     : "=f"(a.x), "=f"(a.y), "=f"(a.z), "=f"(a.w)
                     : "l"(&g_acc[n]));
        w += a.w;
        float* f  = out + 1 + 3 * n;
        float* af = out + 1 + 3 * N + 3 * n;
        f[0]  = -0.5f * a.x;  f[1]  = -0.5f * a.y;  f[2]  = -0.5f * a.z;
        af[0] = a.x;          af[1] = a.y;          af[2] = a.z;
    }

    // CTA reduction of w (16 warps)
    __shared__ float sred[16];
    unsigned lane = threadIdx.x & 31u;
    unsigned warp = threadIdx.x >> 5;
    #pragma unroll
    for (int off = 16; off > 0; off >>= 1)
        w += __shfl_down_sync(0xFFFFFFFFu, w, off);
    if (lane == 0) sred[warp] = w;
    __syncthreads();

    if (threadIdx.x == 0) {
        float v = 0.0f;
        #pragma unroll
        for (int j = 0; j < 16; j++) v += sred[j];
        atomicAdd(&g_misc.pe, (double)v);
        __threadfence();
        unsigned long long old = atomicAdd(&g_misc.bar, 1ULL);
        if (old == 2 * C - 1) {
            // last CTA: all PE contributions fenced-in
            double total = atomicAdd(&g_misc.pe, 0.0);
            out[0] = (float)(0.5 * (total - pe_const));
        }
    }
}

// ---------------------------------------------------------------------------
// Fallback path for N > SCRATCH_CAP (not expected at N=100000).

__global__ void lj_main_direct(const float* __restrict__ bv,
                               const int* __restrict__ dst,
                               float* __restrict__ acc, int E) {
    int e = blockIdx.x * blockDim.x + threadIdx.x;
    float pe = 0.0f;
    if (e < E) {
        float x = bv[3 * e], y = bv[3 * e + 1], z = bv[3 * e + 2];
        int n = dst[e];
        float r2  = fmaf(x, x, fmaf(y, y, z * z));
        float inv = __fdividef(1.0f, r2);
        float c6  = inv * inv * inv;
        float c12 = c6 * c6;
        float fs  = -24.0f * (2.0f * c12 - c6) * inv;
        atomicAdd(acc + 3 * n + 0, fs * x);
        atomicAdd(acc + 3 * n + 1, fs * y);
        atomicAdd(acc + 3 * n + 2, fs * z);
        pe = 4.0f * (c12 - c6);
    }
    #pragma unroll
    for (int off = 16; off > 0; off >>= 1)
        pe += __shfl_down_sync(0xFFFFFFFFu, pe, off);
    if ((threadIdx.x & 31u) == 0) atomicAdd(&g_misc.pe, (double)pe);
}

__global__ void finalize_direct(float* __restrict__ out, int N, double pe_const) {
    int i = blockIdx.x * blockDim.x + threadIdx.x;
    int total = 3 * N;
    if (i < total) out[1 + i] = -0.5f * out[1 + total + i];
    if (i == 0) out[0] = (float)(0.5 * (g_misc.pe - pe_const));
}

// ---------------------------------------------------------------------------

extern "C" void kernel_launch(void* const* d_in, const int* in_sizes, int n_in,
                              void* d_out, int out_size) {
    const float* bv  = (const float*)d_in[0];
    const int*   dst = (const int*)d_in[1];
    float* out = (float*)d_out;

    int E = in_sizes[1];
    int N = (out_size - 1) / 6;
    double pe_const = (double)E * E0_D;

    void *p_acc = nullptr, *p_misc = nullptr;
    cudaGetSymbolAddress(&p_acc, g_acc);
    cudaGetSymbolAddress(&p_misc, g_misc);

    if (N <= SCRATCH_CAP) {
        cudaMemsetAsync(p_acc, 0, (size_t)N * sizeof(float4), 0);
        cudaMemsetAsync(p_misc, 0, sizeof(Misc), 0);
        lj_fused<<<FUSED_CTAS, FUSED_THR>>>(bv, dst, out, E, N, pe_const);
    } else {
        float* acc = out + 1 + 3 * N;
        cudaMemsetAsync(acc, 0, (size_t)(3 * N) * sizeof(float), 0);
        cudaMemsetAsync(p_misc, 0, sizeof(Misc), 0);
        int threads = 256;
        int blocks = (E + threads - 1) / threads;
        lj_main_direct<<<blocks, threads>>>(bv, dst, acc, E);
        int b2 = (3 * N + threads - 1) / threads;
        finalize_direct<<<b2, threads>>>(out, N, pe_const);
    }
}

// round 15
// speedup vs baseline: 1.2552x; 1.1057x over previous
#include <cuda_runtime.h>
#include <cuda_bf16.h>
#include <stdint.h>

// ---------------------------------------------------------------------------
// LennardJones: 1 memset node + 1 fused persistent kernel.
// Outputs (flattened, concatenated):
//   d_out[0]              = potential_energy = 0.5 * (sum_n acc.w - E*e0)
//   d_out[1 .. 1+3N)      = forces          = -0.5 * analytic   (exact identity)
//   d_out[1+3N .. 1+6N)   = analytic_force  = segsum(f_scalar * bv)
//
// Occupancy trend (measured): occ 48.5% -> 53.7us, 71.5% -> 49.2us. This
// round: __launch_bounds__(512,4) => <=32 regs, 2048 thr/SM (100% occ),
// grid 592 co-resident CTAs.
// Cross-replay state: g_bar monotonic arrivals + g_gen epoch base (validated
// R13); g_pe reset by last CTA -> only g_acc needs the memset node.
// ---------------------------------------------------------------------------

#define SCRATCH_CAP 131072   // >= n_nodes (100000)
#define FUSED_CTAS  592      // 148 SMs * 4 CTAs/SM, all co-resident
#define FUSED_THR   512

__device__ float4 g_acc[SCRATCH_CAP];    // per-node {fx,fy,fz,pe_raw}
__device__ double g_pe;                  // PE scratch (reset by last CTA)
__device__ unsigned long long g_bar;     // monotonic barrier arrivals
__device__ unsigned long long g_gen;     // epoch base (advanced by last CTA)

// e0 = 4*((1/3)^12 - (1/3)^6) in double
#define E0_D (-5.479441744238777e-03)

// ---------------------------------------------------------------------------

__device__ __forceinline__ unsigned long long ld_bar() {
    unsigned long long v;
    asm volatile("ld.global.cg.u64 %0, [%1];" : "=l"(v) : "l"(&g_bar));
    return v;
}

__device__ __forceinline__ void edge_op(float x, float y, float z, int n) {
    float r2  = fmaf(x, x, fmaf(y, y, z * z));
    float inv = __fdividef(1.0f, r2);
    float c6  = inv * inv * inv;
    float c12 = c6 * c6;
    float fs  = -24.0f * (2.0f * c12 - c6) * inv;
    float pe  = 4.0f * (c12 - c6);
    float4* p = &g_acc[n];
    asm volatile("red.global.add.v4.f32 [%0], {%1,%2,%3,%4};"
                 :: "l"(p), "f"(fs * x), "f"(fs * y), "f"(fs * z), "f"(pe)
                 : "memory");
}

__global__ void __launch_bounds__(FUSED_THR, 4)
lj_fused(const float* __restrict__ bv, const int* __restrict__ dst,
         float* __restrict__ out, int E, int N, double pe_const) {
    const int t      = blockIdx.x * blockDim.x + threadIdx.x;
    const int stride = gridDim.x * blockDim.x;
    const unsigned long long C    = gridDim.x;
    const unsigned long long base = g_gen;  // stable: set before this launch

    // ---- phase 1: per-edge scatter (g_acc pre-zeroed by memset node) ----
    const int T = (E + 3) >> 2;  // 4-edge tiles
    const float4* bv4  = reinterpret_cast<const float4*>(bv);
    const int4*   dst4 = reinterpret_cast<const int4*>(dst);
    for (int tt = t; tt < T; tt += stride) {
        int e0 = tt * 4;
        if (e0 + 3 < E) {
            float4 a = bv4[3 * tt + 0];
            float4 b = bv4[3 * tt + 1];
            float4 c = bv4[3 * tt + 2];
            int4   d = dst4[tt];
            edge_op(a.x, a.y, a.z, d.x);
            edge_op(a.w, b.x, b.y, d.y);
            edge_op(b.z, b.w, c.x, d.z);
            edge_op(c.y, c.z, c.w, d.w);
        } else {
            for (int e = e0; e < E; e++)
                edge_op(bv[3 * e], bv[3 * e + 1], bv[3 * e + 2], dst[e]);
        }
    }
    __threadfence();

    // ---- grid barrier (all CTAs co-resident by launch_bounds) ----
    __syncthreads();
    if (threadIdx.x == 0) {
        atomicAdd(&g_bar, 1ULL);
        while (ld_bar() < base + C) __nanosleep(128);
    }
    __syncthreads();

    // ---- phase 2: finalize ----
    float w = 0.0f;
    for (int n = t; n < N; n += stride) {
        float4 a;
        asm volatile("ld.global.cg.v4.f32 {%0,%1,%2,%3}, [%4];"
                     : "=f"(a.x), "=f"(a.y), "=f"(a.z), "=f"(a.w)
                     : "l"(&g_acc[n]));
        w += a.w;
        float* f  = out + 1 + 3 * n;
        float* af = out + 1 + 3 * N + 3 * n;
        f[0]  = -0.5f * a.x;  f[1]  = -0.5f * a.y;  f[2]  = -0.5f * a.z;
        af[0] = a.x;          af[1] = a.y;          af[2] = a.z;
    }

    // CTA reduction of w (16 warps)
    __shared__ float sred[16];
    unsigned lane = threadIdx.x & 31u;
    unsigned warp = threadIdx.x >> 5;
    #pragma unroll
    for (int off = 16; off > 0; off >>= 1)
        w += __shfl_down_sync(0xFFFFFFFFu, w, off);
    if (lane == 0) sred[warp] = w;
    __syncthreads();

    if (threadIdx.x == 0) {
        float v = 0.0f;
        #pragma unroll
        for (int j = 0; j < 16; j++) v += sred[j];
        atomicAdd(&g_pe, (double)v);
        __threadfence();
        unsigned long long old = atomicAdd(&g_bar, 1ULL);
        if (old == base + 2 * C - 1) {
            // last CTA: all PE contributions are fenced-in
            double total = atomicAdd(&g_pe, 0.0);
            out[0] = (float)(0.5 * (total - pe_const));
            g_pe  = 0.0;            // reset for next replay
            g_gen = base + 2 * C;   // advance epoch
        }
    }
}

// ---------------------------------------------------------------------------
// Fallback path for N > SCRATCH_CAP (not expected at N=100000).

__global__ void lj_main_direct(const float* __restrict__ bv,
                               const int* __restrict__ dst,
                               float* __restrict__ acc, int E) {
    int e = blockIdx.x * blockDim.x + threadIdx.x;
    float pe = 0.0f;
    if (e < E) {
        float x = bv[3 * e], y = bv[3 * e + 1], z = bv[3 * e + 2];
        int n = dst[e];
        float r2  = fmaf(x, x, fmaf(y, y, z * z));
        float inv = __fdividef(1.0f, r2);
        float c6  = inv * inv * inv;
        float c12 = c6 * c6;
        float fs  = -24.0f * (2.0f * c12 - c6) * inv;
        atomicAdd(acc + 3 * n + 0, fs * x);
        atomicAdd(acc + 3 * n + 1, fs * y);
        atomicAdd(acc + 3 * n + 2, fs * z);
        pe = 4.0f * (c12 - c6);
    }
    #pragma unroll
    for (int off = 16; off > 0; off >>= 1)
        pe += __shfl_down_sync(0xFFFFFFFFu, pe, off);
    if ((threadIdx.x & 31u) == 0) atomicAdd(&g_pe, (double)pe);
}

__global__ void finalize_direct(float* __restrict__ out, int N, double pe_const) {
    int i = blockIdx.x * blockDim.x + threadIdx.x;
    int total = 3 * N;
    if (i < total) out[1 + i] = -0.5f * out[1 + total + i];
    if (i == 0) {
        out[0] = (float)(0.5 * (g_pe - pe_const));
        g_pe = 0.0;
    }
}

// ---------------------------------------------------------------------------

extern "C" void kernel_launch(void* const* d_in, const int* in_sizes, int n_in,
                              void* d_out, int out_size) {
    const float* bv  = (const float*)d_in[0];
    const int*   dst = (const int*)d_in[1];
    float* out = (float*)d_out;

    int E = in_sizes[1];
    int N = (out_size - 1) / 6;
    double pe_const = (double)E * E0_D;

    if (N <= SCRATCH_CAP) {
        void* p_acc = nullptr;
        cudaGetSymbolAddress(&p_acc, g_acc);
        cudaMemsetAsync(p_acc, 0, (size_t)N * sizeof(float4), 0);
        lj_fused<<<FUSED_CTAS, FUSED_THR>>>(bv, dst, out, E, N, pe_const);
    } else {
        float* acc = out + 1 + 3 * N;
        cudaMemsetAsync(acc, 0, (size_t)(3 * N) * sizeof(float), 0);
        int threads = 256;
        int blocks = (E + threads - 1) / threads;
        lj_main_direct<<<blocks, threads>>>(bv, dst, acc, E);
        int b2 = (3 * N + threads - 1) / threads;
        finalize_direct<<<b2, threads>>>(out, N, pe_const);
    }
}